// round 14
// baseline (speedup 1.0000x reference)
#include <cuda_runtime.h>
#include <cuda_bf16.h>

// StixelLoss v14: contiguous-stream layout. Block = (b,c) slab; rows
// interleaved across threads (h = 8i + r) so each block iteration reads
// one 8KB contiguous run per tensor. Bitmask dense scan with multiply-
// spread word reconstruction. L2::256B promoted loads.
// inputs:  (B=256, C=2, H=192, W=256) f32 in (1e-4, 1-1e-4)
// targets: (1, B, C, H, W) f32
// out:     scalar f32 = 1.0*bce_mean + 0.001*cuts + 0.1*dense

#define HH    192
#define WW    256
#define NBC   512
#define NBLK  NBC
#define NTH   512
#define NRES  8               // row residues (h = 8i + r)
#define NIT   (HH / NRES)     // 24 iterations
#define TABN  1216            // 1/d^3 lookup incl. sentinel fold
#define SENT  (-1000)         // pos-SENT in [1001,1190] -> tab 0

__device__ float    g_acc = 0.0f;
__device__ unsigned g_cnt = 0u;

__device__ __forceinline__ float4 ldcg_256(const float4* p) {
    float4 v;
    asm volatile("ld.global.cg.L2::256B.v4.f32 {%0,%1,%2,%3}, [%4];"
                 : "=f"(v.x), "=f"(v.y), "=f"(v.z), "=f"(v.w)
                 : "l"(p));
    return v;
}

__global__ __launch_bounds__(NTH, 4)
void stixel_kernel(const float* __restrict__ inp,
                   const float* __restrict__ tgt,
                   float* __restrict__ out) {
    const int bc = blockIdx.x;               // b*2 + c
    const int c  = bc & 1;
    const int q  = threadIdx.x & 63;         // column quad (cols 4q..4q+3)
    const int r  = threadIdx.x >> 6;         // row residue 0..7

    __shared__ float        tab[TABN];
    __shared__ unsigned int smask[NRES][WW]; // 24-bit masks, bit i <-> h=8i+r
    __shared__ float        sred[16];

    // channel-1 blocks: fill 1/d^3 table (zero outside [1,190])
    if (c == 1) {
        for (int k = threadIdx.x; k < TABN; k += NTH) {
            float fd = (float)k;
            tab[k] = (k >= 1 && k < HH - 1) ? (1.0f / (fd * fd * fd)) : 0.0f;
        }
    }

    // thread walks rows r, r+8, r+16, ... : block iteration i covers rows
    // 8i..8i+7 (all 256 cols) = 8KB contiguous per tensor.
    const size_t base = (size_t)bc * (HH * WW) + (size_t)r * WW + 4 * q;
    const float4* ip4 = (const float4*)(inp + base);
    const float4* tp4 = (const float4*)(tgt + base);

    float bce = 0.0f;
    unsigned int m0 = 0, m1 = 0, m2 = 0, m3 = 0;

    #pragma unroll
    for (int i = 0; i < NIT; ++i) {
        float4 p = ldcg_256(ip4 + i * (NRES * WW / 4));
        float4 t = ldcg_256(tp4 + i * (NRES * WW / 4));
        {
            float lp = __log2f(p.x), l1p = __log2f(1.0f - p.x);
            bce += l1p + t.x * (lp - l1p);
            if (p.x > 0.5f) m0 |= (1u << i);
        }
        {
            float lp = __log2f(p.y), l1p = __log2f(1.0f - p.y);
            bce += l1p + t.y * (lp - l1p);
            if (p.y > 0.5f) m1 |= (1u << i);
        }
        {
            float lp = __log2f(p.z), l1p = __log2f(1.0f - p.z);
            bce += l1p + t.z * (lp - l1p);
            if (p.z > 0.5f) m2 |= (1u << i);
        }
        {
            float lp = __log2f(p.w), l1p = __log2f(1.0f - p.w);
            bce += l1p + t.w * (lp - l1p);
            if (p.w > 0.5f) m3 |= (1u << i);
        }
    }

    float dense = 0.0f;
    int   cuts  = 0;

    if (c == 0) {
        // all 192 rows of channel 0 count (each thread: 24 rows x 4 cols)
        cuts = __popc(m0) + __popc(m1) + __popc(m2) + __popc(m3);
    } else {
        smask[r][4 * q + 0] = m0;
        smask[r][4 * q + 1] = m1;
        smask[r][4 * q + 2] = m2;
        smask[r][4 * q + 3] = m3;
        __syncthreads();

        // thread-per-column full scan (threads 0..255)
        if (threadIdx.x < WW) {
            const int col = threadIdx.x;
            unsigned int mr[NRES];
            #pragma unroll
            for (int rr = 0; rr < NRES; ++rr) mr[rr] = smask[rr][col];

            int prev = SENT;
            #pragma unroll
            for (int w = 0; w < 6; ++w) {
                // reconstruct rows 32w..32w+31: bit (8j+r) from mr[r] bit (4w+j)
                unsigned int W = 0;
                #pragma unroll
                for (int rr = 0; rr < NRES; ++rr) {
                    unsigned int nib = (mr[rr] >> (4 * w)) & 0xFu;
                    W |= ((nib * 0x00204081u) & 0x01010101u) << rr;
                }
                // Reference semantics: hit at h=0 invisible (prev!=0 gate);
                // h=191 excluded (loop runs h<H-1).
                if (w == 0) W &= ~1u;
                if (w == 5) W &= 0x7fffffffu;
                const int rowbase = w * 32;
                while (W) {
                    int b = __ffs(W) - 1;
                    W &= (W - 1);
                    int pos = rowbase + b;
                    dense += tab[pos - prev];  // tab==0 when prev sentinel
                    prev = pos;
                }
            }
        }
    }

    // combine (ALPHA=1, BETA=0.001, GAMMA=0.1); bce is in log2 units
    const float SCALE_BCE = -0.69314718055994531f /
                            (float)((size_t)NBC * HH * WW);
    float val = bce * SCALE_BCE + 0.001f * (float)cuts + 0.1f * dense;

    // block reduction over 512 threads
    #pragma unroll
    for (int off = 16; off > 0; off >>= 1)
        val += __shfl_down_sync(0xffffffffu, val, off);
    const int lane = threadIdx.x & 31;
    const int wid  = threadIdx.x >> 5;
    if (lane == 0) sred[wid] = val;
    __syncthreads();

    if (wid == 0) {
        val = (lane < 16) ? sred[lane] : 0.0f;
        #pragma unroll
        for (int off = 8; off > 0; off >>= 1)
            val += __shfl_down_sync(0xffffffffu, val, off);
        if (lane == 0) {
            atomicAdd(&g_acc, val);
            __threadfence();
            unsigned old = atomicAdd(&g_cnt, 1u);
            if (old == NBLK - 1) {
                // last block: publish result, reset scratch for next replay
                float total = atomicAdd(&g_acc, 0.0f);  // coherent read
                out[0] = total;
                __threadfence();
                g_acc = 0.0f;
                g_cnt = 0u;
            }
        }
    }
}

extern "C" void kernel_launch(void* const* d_in, const int* in_sizes, int n_in,
                              void* d_out, int out_size) {
    const float* inp = (const float*)d_in[0];
    const float* tgt = (const float*)d_in[1];
    float* out = (float*)d_out;

    stixel_kernel<<<NBLK, NTH>>>(inp, tgt, out);
}

// round 15
// speedup vs baseline: 1.0782x; 1.0782x over previous
#include <cuda_runtime.h>
#include <cuda_bf16.h>

// StixelLoss v15: R13 engine with streaming (evict-first) loads.
// inputs:  (B=256, C=2, H=192, W=256) f32 in (1e-4, 1-1e-4)
// targets: (1, B, C, H, W) f32
// out:     scalar f32 = 1.0*bce_mean + 0.001*cuts + 0.1*dense

#define HH    192
#define WW    256
#define NBC   512
#define NBLK  (NBC * 2)       // 1024 blocks: (b, c, w-half)
#define WH    128             // columns per block
#define NQ    32              // float4 quads per block row
#define NSEG  8               // 24-row segments
#define SEGH  24
#define TABN  1216            // 1/d^3 lookup incl. sentinel fold
#define SENT  (-1000)         // prev sentinel: pos-SENT in [1001,1190] -> tab 0

__device__ float    g_acc = 0.0f;
__device__ unsigned g_cnt = 0u;

// Streaming load: evict-first policy (pure single-use stream) + 256B L2
// promotion granule. No reuse anywhere -> don't let 201MB churn L2 LRU.
__device__ __forceinline__ float4 ldcs_256(const float4* p) {
    float4 v;
    asm volatile("ld.global.cs.L2::256B.v4.f32 {%0,%1,%2,%3}, [%4];"
                 : "=f"(v.x), "=f"(v.y), "=f"(v.z), "=f"(v.w)
                 : "l"(p));
    return v;
}

__global__ __launch_bounds__(256, 8)
void stixel_kernel(const float* __restrict__ inp,
                   const float* __restrict__ tgt,
                   float* __restrict__ out) {
    const int bc = blockIdx.x >> 1;          // b*2 + c
    const int wh = blockIdx.x & 1;           // w-half
    const int c  = bc & 1;
    const int q  = threadIdx.x & (NQ - 1);   // quad (cols 4q..4q+3 in half)
    const int s  = threadIdx.x >> 5;         // h-segment 0..7
    const int h0 = s * SEGH;

    __shared__ float        tab[TABN];
    __shared__ unsigned int smask[NSEG][WH];
    __shared__ float        sred[8];

    // channel-1 blocks: fill 1/d^3 table (zero outside [1,190])
    if (c == 1) {
        for (int k = threadIdx.x; k < TABN; k += 256) {
            float fd = (float)k;
            tab[k] = (k >= 1 && k < HH - 1) ? (1.0f / (fd * fd * fd)) : 0.0f;
        }
    }

    const size_t base = (size_t)bc * (HH * WW) + (size_t)h0 * WW
                      + (size_t)wh * WH + 4 * q;
    const float4* ip4 = (const float4*)(inp + base);
    const float4* tp4 = (const float4*)(tgt + base);

    float bce = 0.0f;
    unsigned int m0 = 0, m1 = 0, m2 = 0, m3 = 0;

    // hot loop (identical both channels): log2-domain BCE + mask build
    #pragma unroll
    for (int i = 0; i < SEGH; ++i) {
        float4 p = ldcs_256(ip4 + i * (WW / 4));
        float4 t = ldcs_256(tp4 + i * (WW / 4));
        {
            float lp = __log2f(p.x), l1p = __log2f(1.0f - p.x);
            bce += l1p + t.x * (lp - l1p);
            if (p.x > 0.5f) m0 |= (1u << i);
        }
        {
            float lp = __log2f(p.y), l1p = __log2f(1.0f - p.y);
            bce += l1p + t.y * (lp - l1p);
            if (p.y > 0.5f) m1 |= (1u << i);
        }
        {
            float lp = __log2f(p.z), l1p = __log2f(1.0f - p.z);
            bce += l1p + t.z * (lp - l1p);
            if (p.z > 0.5f) m2 |= (1u << i);
        }
        {
            float lp = __log2f(p.w), l1p = __log2f(1.0f - p.w);
            bce += l1p + t.w * (lp - l1p);
            if (p.w > 0.5f) m3 |= (1u << i);
        }
    }

    float dense = 0.0f;
    int   cuts  = 0;

    if (c == 0) {
        cuts = __popc(m0) + __popc(m1) + __popc(m2) + __popc(m3);
    } else {
        smask[s][4 * q + 0] = m0;
        smask[s][4 * q + 1] = m1;
        smask[s][4 * q + 2] = m2;
        smask[s][4 * q + 3] = m3;
        __syncthreads();

        const int col  = threadIdx.x & (WH - 1);
        const int half = threadIdx.x >> 7;   // 0: rows 0..95, 1: rows 96..191

        int prev = SENT;
        if (half == 1) {
            // initial prev = last hit in rows 0..95 (bit 0 of seg0 invisible)
            unsigned int u3 = smask[3][col];
            unsigned int u2 = smask[2][col];
            unsigned int u1 = smask[1][col];
            unsigned int u0 = smask[0][col] & ~1u;
            if      (u3) prev = 72 + 31 - __clz(u3);
            else if (u2) prev = 48 + 31 - __clz(u2);
            else if (u1) prev = 24 + 31 - __clz(u1);
            else if (u0) prev =      31 - __clz(u0);
        }

        #pragma unroll
        for (int k = 0; k < 4; ++k) {
            unsigned int w = smask[half * 4 + k][col];
            if (half == 0 && k == 0) w &= ~1u;          // h=0 hit invisible
            if (half == 1 && k == 3) w &= ~(1u << 23);  // h=191 excluded
            const int rowbase = (half * 4 + k) * SEGH;
            while (w) {
                int b = __ffs(w) - 1;
                w &= (w - 1);
                int pos = rowbase + b;
                dense += tab[pos - prev];   // tab==0 when prev is sentinel
                prev = pos;
            }
        }
    }

    // combine (ALPHA=1, BETA=0.001, GAMMA=0.1); bce is in log2 units
    const float SCALE_BCE = -0.69314718055994531f /
                            (float)((size_t)NBC * HH * WW);
    float val = bce * SCALE_BCE + 0.001f * (float)cuts + 0.1f * dense;

    // block reduction over 256 threads
    #pragma unroll
    for (int off = 16; off > 0; off >>= 1)
        val += __shfl_down_sync(0xffffffffu, val, off);
    const int lane = threadIdx.x & 31;
    const int wid  = threadIdx.x >> 5;
    if (lane == 0) sred[wid] = val;
    __syncthreads();

    if (wid == 0) {
        val = (lane < 8) ? sred[lane] : 0.0f;
        #pragma unroll
        for (int off = 4; off > 0; off >>= 1)
            val += __shfl_down_sync(0xffffffffu, val, off);
        if (lane == 0) {
            atomicAdd(&g_acc, val);
            __threadfence();
            unsigned old = atomicAdd(&g_cnt, 1u);
            if (old == NBLK - 1) {
                // last block: publish result, reset scratch for next replay
                float total = atomicAdd(&g_acc, 0.0f);  // coherent read
                out[0] = total;
                __threadfence();
                g_acc = 0.0f;
                g_cnt = 0u;
            }
        }
    }
}

extern "C" void kernel_launch(void* const* d_in, const int* in_sizes, int n_in,
                              void* d_out, int out_size) {
    const float* inp = (const float*)d_in[0];
    const float* tgt = (const float*)d_in[1];
    float* out = (float*)d_out;

    stixel_kernel<<<NBLK, 256>>>(inp, tgt, out);
}

// round 16
// speedup vs baseline: 1.0861x; 1.0074x over previous
#include <cuda_runtime.h>
#include <cuda_bf16.h>

// StixelLoss v16 (final probe): R13 engine with read-only (.nc) loads +
// L2::256B promotion. inputs/targets are strictly read-only, never aliased
// with d_out, so the non-coherent path is safe.
// inputs:  (B=256, C=2, H=192, W=256) f32 in (1e-4, 1-1e-4)
// targets: (1, B, C, H, W) f32
// out:     scalar f32 = 1.0*bce_mean + 0.001*cuts + 0.1*dense

#define HH    192
#define WW    256
#define NBC   512
#define NBLK  (NBC * 2)       // 1024 blocks: (b, c, w-half)
#define WH    128             // columns per block
#define NQ    32              // float4 quads per block row
#define NSEG  8               // 24-row segments
#define SEGH  24
#define TABN  1216            // 1/d^3 lookup incl. sentinel fold
#define SENT  (-1000)         // prev sentinel: pos-SENT in [1001,1190] -> tab 0

__device__ float    g_acc = 0.0f;
__device__ unsigned g_cnt = 0u;

// Read-only load, 256B L2 promotion granule (dense stream: every byte of the
// promoted granule is consumed by sibling quads).
__device__ __forceinline__ float4 ldnc_256(const float4* p) {
    float4 v;
    asm volatile("ld.global.nc.L2::256B.v4.f32 {%0,%1,%2,%3}, [%4];"
                 : "=f"(v.x), "=f"(v.y), "=f"(v.z), "=f"(v.w)
                 : "l"(p));
    return v;
}

__global__ __launch_bounds__(256, 8)
void stixel_kernel(const float* __restrict__ inp,
                   const float* __restrict__ tgt,
                   float* __restrict__ out) {
    const int bc = blockIdx.x >> 1;          // b*2 + c
    const int wh = blockIdx.x & 1;           // w-half
    const int c  = bc & 1;
    const int q  = threadIdx.x & (NQ - 1);   // quad (cols 4q..4q+3 in half)
    const int s  = threadIdx.x >> 5;         // h-segment 0..7
    const int h0 = s * SEGH;

    __shared__ float        tab[TABN];
    __shared__ unsigned int smask[NSEG][WH];
    __shared__ float        sred[8];

    // channel-1 blocks: fill 1/d^3 table (zero outside [1,190])
    if (c == 1) {
        for (int k = threadIdx.x; k < TABN; k += 256) {
            float fd = (float)k;
            tab[k] = (k >= 1 && k < HH - 1) ? (1.0f / (fd * fd * fd)) : 0.0f;
        }
    }

    const size_t base = (size_t)bc * (HH * WW) + (size_t)h0 * WW
                      + (size_t)wh * WH + 4 * q;
    const float4* ip4 = (const float4*)(inp + base);
    const float4* tp4 = (const float4*)(tgt + base);

    float bce = 0.0f;
    unsigned int m0 = 0, m1 = 0, m2 = 0, m3 = 0;

    // hot loop (identical both channels): log2-domain BCE + mask build
    #pragma unroll
    for (int i = 0; i < SEGH; ++i) {
        float4 p = ldnc_256(ip4 + i * (WW / 4));
        float4 t = ldnc_256(tp4 + i * (WW / 4));
        {
            float lp = __log2f(p.x), l1p = __log2f(1.0f - p.x);
            bce += l1p + t.x * (lp - l1p);
            if (p.x > 0.5f) m0 |= (1u << i);
        }
        {
            float lp = __log2f(p.y), l1p = __log2f(1.0f - p.y);
            bce += l1p + t.y * (lp - l1p);
            if (p.y > 0.5f) m1 |= (1u << i);
        }
        {
            float lp = __log2f(p.z), l1p = __log2f(1.0f - p.z);
            bce += l1p + t.z * (lp - l1p);
            if (p.z > 0.5f) m2 |= (1u << i);
        }
        {
            float lp = __log2f(p.w), l1p = __log2f(1.0f - p.w);
            bce += l1p + t.w * (lp - l1p);
            if (p.w > 0.5f) m3 |= (1u << i);
        }
    }

    float dense = 0.0f;
    int   cuts  = 0;

    if (c == 0) {
        cuts = __popc(m0) + __popc(m1) + __popc(m2) + __popc(m3);
    } else {
        smask[s][4 * q + 0] = m0;
        smask[s][4 * q + 1] = m1;
        smask[s][4 * q + 2] = m2;
        smask[s][4 * q + 3] = m3;
        __syncthreads();

        const int col  = threadIdx.x & (WH - 1);
        const int half = threadIdx.x >> 7;   // 0: rows 0..95, 1: rows 96..191

        int prev = SENT;
        if (half == 1) {
            // initial prev = last hit in rows 0..95 (bit 0 of seg0 invisible)
            unsigned int u3 = smask[3][col];
            unsigned int u2 = smask[2][col];
            unsigned int u1 = smask[1][col];
            unsigned int u0 = smask[0][col] & ~1u;
            if      (u3) prev = 72 + 31 - __clz(u3);
            else if (u2) prev = 48 + 31 - __clz(u2);
            else if (u1) prev = 24 + 31 - __clz(u1);
            else if (u0) prev =      31 - __clz(u0);
        }

        #pragma unroll
        for (int k = 0; k < 4; ++k) {
            unsigned int w = smask[half * 4 + k][col];
            if (half == 0 && k == 0) w &= ~1u;          // h=0 hit invisible
            if (half == 1 && k == 3) w &= ~(1u << 23);  // h=191 excluded
            const int rowbase = (half * 4 + k) * SEGH;
            while (w) {
                int b = __ffs(w) - 1;
                w &= (w - 1);
                int pos = rowbase + b;
                dense += tab[pos - prev];   // tab==0 when prev is sentinel
                prev = pos;
            }
        }
    }

    // combine (ALPHA=1, BETA=0.001, GAMMA=0.1); bce is in log2 units
    const float SCALE_BCE = -0.69314718055994531f /
                            (float)((size_t)NBC * HH * WW);
    float val = bce * SCALE_BCE + 0.001f * (float)cuts + 0.1f * dense;

    // block reduction over 256 threads
    #pragma unroll
    for (int off = 16; off > 0; off >>= 1)
        val += __shfl_down_sync(0xffffffffu, val, off);
    const int lane = threadIdx.x & 31;
    const int wid  = threadIdx.x >> 5;
    if (lane == 0) sred[wid] = val;
    __syncthreads();

    if (wid == 0) {
        val = (lane < 8) ? sred[lane] : 0.0f;
        #pragma unroll
        for (int off = 4; off > 0; off >>= 1)
            val += __shfl_down_sync(0xffffffffu, val, off);
        if (lane == 0) {
            atomicAdd(&g_acc, val);
            __threadfence();
            unsigned old = atomicAdd(&g_cnt, 1u);
            if (old == NBLK - 1) {
                // last block: publish result, reset scratch for next replay
                float total = atomicAdd(&g_acc, 0.0f);  // coherent read
                out[0] = total;
                __threadfence();
                g_acc = 0.0f;
                g_cnt = 0u;
            }
        }
    }
}

extern "C" void kernel_launch(void* const* d_in, const int* in_sizes, int n_in,
                              void* d_out, int out_size) {
    const float* inp = (const float*)d_in[0];
    const float* tgt = (const float*)d_in[1];
    float* out = (float*)d_out;

    stixel_kernel<<<NBLK, 256>>>(inp, tgt, out);
}